// round 13
// baseline (speedup 1.0000x reference)
#include <cuda_runtime.h>
#include <cstdint>

// Problem: inputs [8,128,128,64] f32, beta [64,16] f32
// out[e, c] = inputs[e] * u[e%64, c],  u = beta^2 / rowsum(beta^2)
// out flat: 2^25 float4s = 2^17 tiles of 256 float4 (4 KiB).
//
// R13: warp-private TMA store pipeline. Each warp owns a 3-deep ring of
// 4 KiB smem tiles + its own bulk_group (elected lane). Steady state has
// NO block-wide barriers: fill runs ahead while cp.async.bulk drains up
// to 3 tiles; recycle throttled by wait_group.read 2 + __syncwarp.
// Tiles grid-strided across all warps -> dense chip-wide output sweep.

#define D_DIM 64
#define BLOCKS 304                 // 152 SMs x 2 resident
#define THREADS 256                // 8 warps
#define WARPS_PER_BLOCK 8
#define NW (BLOCKS * WARPS_PER_BLOCK)   // 2432 warps total
#define TILE_F4 256                // float4 per tile (4 KiB), multiple of 256
#define TILES (1u << 17)           // total tiles
#define DEPTH 3                    // ring depth per warp
#define SMEM_BYTES (WARPS_PER_BLOCK * DEPTH * TILE_F4 * 16)   // 98304

extern __shared__ float4 s_ring[];   // [warp][DEPTH][256] float4

__global__ void fused_broadcast_mul_tma(
    const float* __restrict__ in, const float* __restrict__ beta,
    float* __restrict__ out) {
    __shared__ float su[D_DIM * 16];   // 4 KiB u table

    const unsigned int tid = threadIdx.x;
    const unsigned int widx = tid >> 5;
    const unsigned int lane = tid & 31u;

    // ---- build u table once per block (threads 0..63, one row each) ----
    if (tid < D_DIM) {
        float b[16];
        float s = 0.0f;
#pragma unroll
        for (int c = 0; c < 16; ++c) {
            float v = beta[tid * 16 + c];
            b[c] = v * v;
            s += b[c];
        }
        float inv = 1.0f / s;
#pragma unroll
        for (int c = 0; c < 16; ++c) su[tid * 16 + c] = b[c] * inv;
    }
    __syncthreads();   // only block-wide barrier in the kernel

    // ---- preload this lane's 8 u quarters (rows (lane>>2)+8k, quarter lane&3)
    const unsigned int j = lane & 3u;
    float4 u[8];
#pragma unroll
    for (int k = 0; k < 8; ++k) {
        unsigned int i = (lane >> 2) + 8u * k;
        u[k] = reinterpret_cast<const float4*>(su)[i * 4 + j];
    }

    float4* ring = s_ring + (widx * DEPTH) * TILE_F4;
    uint32_t ring_s32;
    asm("{ .reg .u64 t; cvta.to.shared.u64 t, %1; cvt.u32.u64 %0, t; }"
        : "=r"(ring_s32) : "l"(ring));

    const unsigned int W = blockIdx.x * WARPS_PER_BLOCK + widx;

    int t = 0;
    for (unsigned int tt = W; tt < TILES; tt += NW, ++t) {
        const int b = t % DEPTH;

        // Throttle ring reuse: oldest pending tile must be read out of smem.
        if (t >= DEPTH) {
            if (lane == 0)
                asm volatile("cp.async.bulk.wait_group.read %0;"
                             :: "n"(DEPTH - 1) : "memory");
        }
        __syncwarp();

        // ---- fill tile: 8 batched LDG.32, then 8 FMUL4+STS.128 ----
        // tile float4 base tb = tt*256 (multiple of 256); lane handles
        // float4s tb+lane+32k -> input elem tt*64 + (lane>>2) + 8k.
        const float* ip = in + ((size_t)tt << 6) + (lane >> 2);
        float x[8];
#pragma unroll
        for (int k = 0; k < 8; ++k) x[k] = __ldg(ip + 8 * k);

        float4* sb = ring + b * TILE_F4;
#pragma unroll
        for (int k = 0; k < 8; ++k) {
            sb[lane + 32 * k] = make_float4(x[k] * u[k].x, x[k] * u[k].y,
                                            x[k] * u[k].z, x[k] * u[k].w);
        }

        // ---- hand tile to async proxy ----
        asm volatile("fence.proxy.async.shared::cta;" ::: "memory");
        __syncwarp();
        if (lane == 0) {
            const float* gdst = out + ((size_t)tt << 10);   // tt*1024 floats
            uint32_t ssrc = ring_s32 + b * (TILE_F4 * 16);
            asm volatile(
                "cp.async.bulk.global.shared::cta.bulk_group [%0], [%1], %2;"
                :: "l"(gdst), "r"(ssrc), "n"(TILE_F4 * 16) : "memory");
            asm volatile("cp.async.bulk.commit_group;" ::: "memory");
        }
    }

    // Drain all pending bulk stores before exit.
    if (lane == 0)
        asm volatile("cp.async.bulk.wait_group 0;" ::: "memory");
}

extern "C" void kernel_launch(void* const* d_in, const int* in_sizes, int n_in,
                              void* d_out, int out_size) {
    const float* inputs = (const float*)d_in[0];  // 8*128*128*64 = 8388608
    const float* beta   = (const float*)d_in[1];  // 64*16 = 1024
    float* out = (float*)d_out;

    static int attr_set = 0;
    if (!attr_set) {
        cudaFuncSetAttribute(fused_broadcast_mul_tma,
                             cudaFuncAttributeMaxDynamicSharedMemorySize,
                             SMEM_BYTES);
        attr_set = 1;
    }
    fused_broadcast_mul_tma<<<BLOCKS, THREADS, SMEM_BYTES>>>(inputs, beta, out);
}

// round 14
// speedup vs baseline: 1.0846x; 1.0846x over previous
#include <cuda_runtime.h>

// Problem: inputs [8,128,128,64] f32, beta [64,16] f32
// out[e, c] = inputs[e] * u[e%64, c],  u = beta^2 / rowsum(beta^2)
// out flat: n4 = 2^25 float4s. (i = (g>>2)&63, j = g&3) has period 256 in g;
// grid stride is a multiple of 256 -> per-thread u is loop-invariant.
//
// R14 = R3 (best, 92.3us) + explicit software pipelining across the batch
// boundary: batch p+1's 8 loads issue BEFORE batch p's 8 stores, so the
// L1tex queue never drains between passes.

#define D_DIM 64
#define BLOCKS 1024
#define THREADS 256
#define STRIDE (BLOCKS * THREADS)      // 2^18 float4s per grid step
#define ITERS 128                      // 2^25 / STRIDE
#define BATCH 8
#define PASSES (ITERS / BATCH)         // 16

__global__ void __launch_bounds__(THREADS) fused_broadcast_mul(
    const float* __restrict__ in, const float* __restrict__ beta,
    float4* __restrict__ out) {
    unsigned int g = blockIdx.x * THREADS + threadIdx.x;
    const unsigned int i = (g >> 2) & (D_DIM - 1);  // beta row
    const unsigned int j = g & 3u;                  // float4 quarter of the row

    // ---- one-time prologue: this thread's u quarter, in registers ----
    const float4* br = reinterpret_cast<const float4*>(beta) + i * 4;
    float4 q0 = __ldg(br + 0);
    float4 q1 = __ldg(br + 1);
    float4 q2 = __ldg(br + 2);
    float4 q3 = __ldg(br + 3);
    float s = q0.x * q0.x + q0.y * q0.y + q0.z * q0.z + q0.w * q0.w
            + q1.x * q1.x + q1.y * q1.y + q1.z * q1.z + q1.w * q1.w
            + q2.x * q2.x + q2.y * q2.y + q2.z * q2.z + q2.w * q2.w
            + q3.x * q3.x + q3.y * q3.y + q3.z * q3.z + q3.w * q3.w;
    float inv = 1.0f / s;
    float4 bq = (j == 0) ? q0 : (j == 1) ? q1 : (j == 2) ? q2 : q3;
    const float4 u = make_float4(bq.x * bq.x * inv, bq.y * bq.y * inv,
                                 bq.z * bq.z * inv, bq.w * bq.w * inv);

    // ---- software-pipelined stream: loads of pass p+1 before stores of p ----
    const float* ip = in + (g >> 2);
    float4* op = out + g;

    float x[BATCH];
#pragma unroll
    for (int k = 0; k < BATCH; ++k)
        x[k] = __ldg(ip + k * (STRIDE / 4));        // prologue: batch 0 loads
    ip += (STRIDE / 4) * BATCH;

    for (int p = 0; p < PASSES - 1; ++p) {
        float y[BATCH];
#pragma unroll
        for (int k = 0; k < BATCH; ++k)             // next batch's loads first
            y[k] = __ldg(ip + k * (STRIDE / 4));
#pragma unroll
        for (int k = 0; k < BATCH; ++k) {           // then this batch's stores
            float4 r = make_float4(x[k] * u.x, x[k] * u.y,
                                   x[k] * u.z, x[k] * u.w);
            __stcs(op + k * STRIDE, r);
        }
#pragma unroll
        for (int k = 0; k < BATCH; ++k) x[k] = y[k];
        ip += (STRIDE / 4) * BATCH;
        op += STRIDE * BATCH;
    }

    // epilogue: final batch's stores
#pragma unroll
    for (int k = 0; k < BATCH; ++k) {
        float4 r = make_float4(x[k] * u.x, x[k] * u.y,
                               x[k] * u.z, x[k] * u.w);
        __stcs(op + k * STRIDE, r);
    }
}

extern "C" void kernel_launch(void* const* d_in, const int* in_sizes, int n_in,
                              void* d_out, int out_size) {
    const float* inputs = (const float*)d_in[0];  // 8*128*128*64 = 8388608
    const float* beta   = (const float*)d_in[1];  // 64*16 = 1024
    float4* out = (float4*)d_out;

    fused_broadcast_mul<<<BLOCKS, THREADS>>>(inputs, beta, out);
}

// round 15
// speedup vs baseline: 1.1063x; 1.0201x over previous
#include <cuda_runtime.h>

// Problem: inputs [8,128,128,64] f32, beta [64,16] f32
// out[e, c] = inputs[e] * u[e%64, c],  u = beta^2 / rowsum(beta^2)
// out flat: n4 = 2^25 float4s. (i = (g>>2)&63, j = g&3) has period 256 in g,
// and the grid stride is a multiple of 256 -> per-thread u is loop-invariant.
//
// FINAL (R3 configuration, best measured: 92.3 us ≈ 5.5 TB/s effective).
// Eleven probed variants (v8 stores, .wb, TMA bulk-store pipelines, reg caps,
// occupancy/grid reshapes, software pipelining) all pinned at DRAM 66-68% /
// ~5.3 TB/s: this op sits at the HBM3e write-stream ceiling, and this shape
// is the best draw of that family.

#define D_DIM 64
#define BLOCKS 1024
#define THREADS 256
#define STRIDE (BLOCKS * THREADS)      // 2^18 float4s per grid step
#define ITERS 128                      // 2^25 / STRIDE
#define BATCH 8                        // front-loaded independent loads
#define PASSES (ITERS / BATCH)         // 16

__global__ void __launch_bounds__(THREADS) fused_broadcast_mul(
    const float* __restrict__ in, const float* __restrict__ beta,
    float4* __restrict__ out) {
    unsigned int g = blockIdx.x * THREADS + threadIdx.x;
    const unsigned int i = (g >> 2) & (D_DIM - 1);  // beta row
    const unsigned int j = g & 3u;                  // float4 quarter of the row

    // ---- one-time prologue: this thread's u quarter, in registers ----
    const float4* br = reinterpret_cast<const float4*>(beta) + i * 4;
    float4 q0 = __ldg(br + 0);
    float4 q1 = __ldg(br + 1);
    float4 q2 = __ldg(br + 2);
    float4 q3 = __ldg(br + 3);
    float s = q0.x * q0.x + q0.y * q0.y + q0.z * q0.z + q0.w * q0.w
            + q1.x * q1.x + q1.y * q1.y + q1.z * q1.z + q1.w * q1.w
            + q2.x * q2.x + q2.y * q2.y + q2.z * q2.z + q2.w * q2.w
            + q3.x * q3.x + q3.y * q3.y + q3.z * q3.z + q3.w * q3.w;
    float inv = 1.0f / s;
    float4 bq = (j == 0) ? q0 : (j == 1) ? q1 : (j == 2) ? q2 : q3;
    const float4 u = make_float4(bq.x * bq.x * inv, bq.y * bq.y * inv,
                                 bq.z * bq.z * inv, bq.w * bq.w * inv);

    // ---- 16 passes: 8 independent loads, then 8 FMUL+STG.128 ----
    const float* ip = in + (g >> 2);
    float4* op = out + g;

    for (int p = 0; p < PASSES; ++p) {
        float x[BATCH];
#pragma unroll
        for (int k = 0; k < BATCH; ++k)
            x[k] = __ldg(ip + k * (STRIDE / 4));   // input fits L2 -> mostly hits
#pragma unroll
        for (int k = 0; k < BATCH; ++k) {
            float4 r = make_float4(x[k] * u.x, x[k] * u.y,
                                   x[k] * u.z, x[k] * u.w);
            __stcs(op + k * STRIDE, r);            // evict-first write stream
        }
        ip += (STRIDE / 4) * BATCH;
        op += STRIDE * BATCH;
    }
}

extern "C" void kernel_launch(void* const* d_in, const int* in_sizes, int n_in,
                              void* d_out, int out_size) {
    const float* inputs = (const float*)d_in[0];  // 8*128*128*64 = 8388608
    const float* beta   = (const float*)d_in[1];  // 64*16 = 1024
    float4* out = (float4*)d_out;

    fused_broadcast_mul<<<BLOCKS, THREADS>>>(inputs, beta, out);
}

// round 16
// speedup vs baseline: 1.1079x; 1.0014x over previous
#include <cuda_runtime.h>

// Problem: inputs [8,128,128,64] f32, beta [64,16] f32
// out[e, c] = inputs[e] * u[e%64, c],  u = beta^2 / rowsum(beta^2)
// out flat: n4 = 2^25 float4s. (i = (g>>2)&63, j = g&3) has period 256 in g,
// and the grid stride is a multiple of 256 -> per-thread u is loop-invariant.
//
// R16: single-variable probe off the confirmed optimum (R3/R15, 92.3 us):
// same body (batch-8 front-loaded loads, .cs stores, no reg cap), block
// count 1024 -> 2048 (ITERS 128 -> 64, PASSES 16 -> 8). Isolates the
// block-count axis at the winning batch size.

#define D_DIM 64
#define BLOCKS 2048
#define THREADS 256
#define STRIDE (BLOCKS * THREADS)      // 2^19 float4s per grid step
#define ITERS 64                       // 2^25 / STRIDE
#define BATCH 8                        // front-loaded independent loads
#define PASSES (ITERS / BATCH)         // 8

__global__ void __launch_bounds__(THREADS) fused_broadcast_mul(
    const float* __restrict__ in, const float* __restrict__ beta,
    float4* __restrict__ out) {
    unsigned int g = blockIdx.x * THREADS + threadIdx.x;
    const unsigned int i = (g >> 2) & (D_DIM - 1);  // beta row
    const unsigned int j = g & 3u;                  // float4 quarter of the row

    // ---- one-time prologue: this thread's u quarter, in registers ----
    const float4* br = reinterpret_cast<const float4*>(beta) + i * 4;
    float4 q0 = __ldg(br + 0);
    float4 q1 = __ldg(br + 1);
    float4 q2 = __ldg(br + 2);
    float4 q3 = __ldg(br + 3);
    float s = q0.x * q0.x + q0.y * q0.y + q0.z * q0.z + q0.w * q0.w
            + q1.x * q1.x + q1.y * q1.y + q1.z * q1.z + q1.w * q1.w
            + q2.x * q2.x + q2.y * q2.y + q2.z * q2.z + q2.w * q2.w
            + q3.x * q3.x + q3.y * q3.y + q3.z * q3.z + q3.w * q3.w;
    float inv = 1.0f / s;
    float4 bq = (j == 0) ? q0 : (j == 1) ? q1 : (j == 2) ? q2 : q3;
    const float4 u = make_float4(bq.x * bq.x * inv, bq.y * bq.y * inv,
                                 bq.z * bq.z * inv, bq.w * bq.w * inv);

    // ---- 8 passes: 8 independent loads, then 8 FMUL+STG.128 ----
    const float* ip = in + (g >> 2);
    float4* op = out + g;

    for (int p = 0; p < PASSES; ++p) {
        float x[BATCH];
#pragma unroll
        for (int k = 0; k < BATCH; ++k)
            x[k] = __ldg(ip + k * (STRIDE / 4));   // input fits L2 -> mostly hits
#pragma unroll
        for (int k = 0; k < BATCH; ++k) {
            float4 r = make_float4(x[k] * u.x, x[k] * u.y,
                                   x[k] * u.z, x[k] * u.w);
            __stcs(op + k * STRIDE, r);            // evict-first write stream
        }
        ip += (STRIDE / 4) * BATCH;
        op += STRIDE * BATCH;
    }
}

extern "C" void kernel_launch(void* const* d_in, const int* in_sizes, int n_in,
                              void* d_out, int out_size) {
    const float* inputs = (const float*)d_in[0];  // 8*128*128*64 = 8388608
    const float* beta   = (const float*)d_in[1];  // 64*16 = 1024
    float4* out = (float4*)d_out;

    fused_broadcast_mul<<<BLOCKS, THREADS>>>(inputs, beta, out);
}

// round 17
// speedup vs baseline: 1.1593x; 1.0465x over previous
#include <cuda_runtime.h>

// Problem: inputs [8,128,128,64] f32, beta [64,16] f32
// out[e, c] = inputs[e] * u[e%64, c],  u = beta^2 / rowsum(beta^2)
// out flat: n4 = 2^25 float4s. (i = (g>>2)&63, j = g&3) has period 256 in g,
// and the grid stride is a multiple of 256 -> per-thread u is loop-invariant.
//
// R17: continue the winning block-count axis (1024: 92.8 kernel-us,
// 2048: 91.6) -> 4096 blocks (ITERS=32, PASSES=4). Everything else is the
// confirmed-optimal body: batch-8 front-loaded loads, .cs stores, no reg cap.

#define D_DIM 64
#define BLOCKS 4096
#define THREADS 256
#define STRIDE (BLOCKS * THREADS)      // 2^20 float4s per grid step
#define ITERS 32                       // 2^25 / STRIDE
#define BATCH 8                        // front-loaded independent loads
#define PASSES (ITERS / BATCH)         // 4

__global__ void __launch_bounds__(THREADS) fused_broadcast_mul(
    const float* __restrict__ in, const float* __restrict__ beta,
    float4* __restrict__ out) {
    unsigned int g = blockIdx.x * THREADS + threadIdx.x;
    const unsigned int i = (g >> 2) & (D_DIM - 1);  // beta row
    const unsigned int j = g & 3u;                  // float4 quarter of the row

    // ---- one-time prologue: this thread's u quarter, in registers ----
    const float4* br = reinterpret_cast<const float4*>(beta) + i * 4;
    float4 q0 = __ldg(br + 0);
    float4 q1 = __ldg(br + 1);
    float4 q2 = __ldg(br + 2);
    float4 q3 = __ldg(br + 3);
    float s = q0.x * q0.x + q0.y * q0.y + q0.z * q0.z + q0.w * q0.w
            + q1.x * q1.x + q1.y * q1.y + q1.z * q1.z + q1.w * q1.w
            + q2.x * q2.x + q2.y * q2.y + q2.z * q2.z + q2.w * q2.w
            + q3.x * q3.x + q3.y * q3.y + q3.z * q3.z + q3.w * q3.w;
    float inv = 1.0f / s;
    float4 bq = (j == 0) ? q0 : (j == 1) ? q1 : (j == 2) ? q2 : q3;
    const float4 u = make_float4(bq.x * bq.x * inv, bq.y * bq.y * inv,
                                 bq.z * bq.z * inv, bq.w * bq.w * inv);

    // ---- 4 passes: 8 independent loads, then 8 FMUL+STG.128 ----
    const float* ip = in + (g >> 2);
    float4* op = out + g;

    for (int p = 0; p < PASSES; ++p) {
        float x[BATCH];
#pragma unroll
        for (int k = 0; k < BATCH; ++k)
            x[k] = __ldg(ip + k * (STRIDE / 4));   // input fits L2 -> mostly hits
#pragma unroll
        for (int k = 0; k < BATCH; ++k) {
            float4 r = make_float4(x[k] * u.x, x[k] * u.y,
                                   x[k] * u.z, x[k] * u.w);
            __stcs(op + k * STRIDE, r);            // evict-first write stream
        }
        ip += (STRIDE / 4) * BATCH;
        op += STRIDE * BATCH;
    }
}

extern "C" void kernel_launch(void* const* d_in, const int* in_sizes, int n_in,
                              void* d_out, int out_size) {
    const float* inputs = (const float*)d_in[0];  // 8*128*128*64 = 8388608
    const float* beta   = (const float*)d_in[1];  // 64*16 = 1024
    float4* out = (float4*)d_out;

    fused_broadcast_mul<<<BLOCKS, THREADS>>>(inputs, beta, out);
}